// round 1
// baseline (speedup 1.0000x reference)
#include <cuda_runtime.h>
#include <cstdint>
#include <cstdio>

// Problem constants
#define BB 8
#define TT 256
#define MM 64
#define DD 512
#define HH 8
#define DKK 64
#define NROWS (BB*TT*MM)        // 131072
#define NBT   (BB*TT)           // 2048
#define NBTH  (BB*TT*HH)        // 16384

// Scratch (device globals: allocation-free)
__device__ float g_q[NBTH*MM*DKK];   // (bt,h,m,dk)
__device__ float g_k[NBTH*MM*DKK];
__device__ float g_v[NBTH*MM*DKK];
__device__ float g_a[NROWS*DD];      // (btm, d) attention output

__device__ __forceinline__ uint32_t f2tf32(float f) {
    uint32_t r;
    asm("cvt.rna.tf32.f32 %0, %1;" : "=r"(r) : "f"(f));
    return r;
}

__device__ __forceinline__ void mma_tf32(float* c,
    uint32_t a0, uint32_t a1, uint32_t a2, uint32_t a3,
    uint32_t b0, uint32_t b1)
{
    asm volatile(
        "mma.sync.aligned.m16n8k8.row.col.f32.tf32.tf32.f32 "
        "{%0,%1,%2,%3}, {%4,%5,%6,%7}, {%8,%9}, {%0,%1,%2,%3};"
        : "+f"(c[0]), "+f"(c[1]), "+f"(c[2]), "+f"(c[3])
        : "r"(a0), "r"(a1), "r"(a2), "r"(a3), "r"(b0), "r"(b1));
}

// ---------------------------------------------------------------------------
// GEMM: Y = X @ W^T + bias.  X: (NROWS, 512) fp32, W: (512, 512) fp32 row-major.
// Tile: BM=128, BN=64, BK=32. 256 threads = 8 warps (4x2), warp tile 32x32.
// MODE 0: store permuted to (bt, h, m, dk) layout (for q/k/v).
// MODE 1: store row-major (btm, d).
// ---------------------------------------------------------------------------
template<int MODE>
__global__ __launch_bounds__(256)
void gemm_tf32(const float* __restrict__ X, const float* __restrict__ W,
               const float* __restrict__ bias, float* __restrict__ Y)
{
    __shared__ uint32_t Xs[128*36];
    __shared__ uint32_t Ws[64*36];

    const int tid  = threadIdx.x;
    const int m0   = blockIdx.y * 128;
    const int n0   = blockIdx.x * 64;
    const int wid  = tid >> 5, lane = tid & 31;
    const int g    = lane >> 2, tg = lane & 3;
    const int wm   = (wid & 3) * 32;      // warp m offset within tile
    const int wn   = (wid >> 2) * 32;     // warp n offset within tile

    float acc[2][4][4];
    #pragma unroll
    for (int a = 0; a < 2; a++)
        #pragma unroll
        for (int b = 0; b < 4; b++)
            #pragma unroll
            for (int c = 0; c < 4; c++) acc[a][b][c] = 0.f;

    for (int kt = 0; kt < 512; kt += 32) {
        // stage X tile (128x32), convert to tf32
        #pragma unroll
        for (int i = 0; i < 4; i++) {
            int idx = tid + i * 256;
            int r = idx >> 3, c = (idx & 7) * 4;
            float4 xv = *(const float4*)(X + (size_t)(m0 + r) * 512 + kt + c);
            Xs[r*36 + c + 0] = f2tf32(xv.x);
            Xs[r*36 + c + 1] = f2tf32(xv.y);
            Xs[r*36 + c + 2] = f2tf32(xv.z);
            Xs[r*36 + c + 3] = f2tf32(xv.w);
        }
        // stage W tile (64x32)
        #pragma unroll
        for (int i = 0; i < 2; i++) {
            int idx = tid + i * 256;
            int r = idx >> 3, c = (idx & 7) * 4;
            float4 wv = *(const float4*)(W + (size_t)(n0 + r) * 512 + kt + c);
            Ws[r*36 + c + 0] = f2tf32(wv.x);
            Ws[r*36 + c + 1] = f2tf32(wv.y);
            Ws[r*36 + c + 2] = f2tf32(wv.z);
            Ws[r*36 + c + 3] = f2tf32(wv.w);
        }
        __syncthreads();

        #pragma unroll
        for (int ks = 0; ks < 32; ks += 8) {
            uint32_t a[2][4];
            #pragma unroll
            for (int im = 0; im < 2; im++) {
                int row = wm + im * 16;
                a[im][0] = Xs[(row + g    ) * 36 + ks + tg    ];
                a[im][1] = Xs[(row + g + 8) * 36 + ks + tg    ];
                a[im][2] = Xs[(row + g    ) * 36 + ks + tg + 4];
                a[im][3] = Xs[(row + g + 8) * 36 + ks + tg + 4];
            }
            #pragma unroll
            for (int in = 0; in < 4; in++) {
                int nr = wn + in * 8 + g;
                uint32_t b0 = Ws[nr * 36 + ks + tg    ];
                uint32_t b1 = Ws[nr * 36 + ks + tg + 4];
                mma_tf32(acc[0][in], a[0][0], a[0][1], a[0][2], a[0][3], b0, b1);
                mma_tf32(acc[1][in], a[1][0], a[1][1], a[1][2], a[1][3], b0, b1);
            }
        }
        __syncthreads();
    }

    // epilogue
    #pragma unroll
    for (int im = 0; im < 2; im++) {
        #pragma unroll
        for (int in = 0; in < 4; in++) {
            int col = n0 + wn + in * 8 + 2 * tg;
            float bv0 = bias[col], bv1 = bias[col + 1];
            int r0 = m0 + wm + im * 16 + g;
            int r1 = r0 + 8;
            float v00 = acc[im][in][0] + bv0;
            float v01 = acc[im][in][1] + bv1;
            float v10 = acc[im][in][2] + bv0;
            float v11 = acc[im][in][3] + bv1;
            if (MODE == 0) {
                // dest = bt*32768 + h*4096 + m*64 + dk
                int h  = col >> 6, dk = col & 63;
                {
                    int bt = r0 >> 6, m = r0 & 63;
                    size_t d = (size_t)bt * 32768 + h * 4096 + m * 64 + dk;
                    Y[d] = v00; Y[d + 1] = v01;
                }
                {
                    int bt = r1 >> 6, m = r1 & 63;
                    size_t d = (size_t)bt * 32768 + h * 4096 + m * 64 + dk;
                    Y[d] = v10; Y[d + 1] = v11;
                }
            } else {
                Y[(size_t)r0 * 512 + col]     = v00;
                Y[(size_t)r0 * 512 + col + 1] = v01;
                Y[(size_t)r1 * 512 + col]     = v10;
                Y[(size_t)r1 * 512 + col + 1] = v11;
            }
        }
    }
}

// ---------------------------------------------------------------------------
// Attention: one CTA per (bt, h). q,k,v tiles are 64x64 fp32 at g_q + bth*4096.
// 128 threads = 4 warps; warp w handles score/output rows [16w, 16w+16).
// scores = q @ k^T / 8 -> softmax (register, shfl over quad) -> p @ v.
// Writes g_a[(bt*64+m)*512 + h*64 + dk].
// ---------------------------------------------------------------------------
__global__ __launch_bounds__(128)
void attn_kernel(float* __restrict__ out_a)
{
    const int bth = blockIdx.x;
    const int bt = bth >> 3, h = bth & 7;
    const float* qg = g_q + (size_t)bth * 4096;
    const float* kg = g_k + (size_t)bth * 4096;
    const float* vg = g_v + (size_t)bth * 4096;

    extern __shared__ uint32_t sh[];
    uint32_t* qs = sh;
    uint32_t* ks = sh + 64 * 68;
    uint32_t* vs = sh + 2 * 64 * 68;
    uint32_t* ss = sh + 3 * 64 * 68;

    const int tid = threadIdx.x;

    // stage q,k,v as tf32
    #pragma unroll
    for (int i = 0; i < 8; i++) {
        int idx = tid + i * 128;
        int r = idx >> 4, c = (idx & 15) * 4;
        float4 a = *(const float4*)(qg + r * 64 + c);
        qs[r*68+c] = f2tf32(a.x); qs[r*68+c+1] = f2tf32(a.y);
        qs[r*68+c+2] = f2tf32(a.z); qs[r*68+c+3] = f2tf32(a.w);
        float4 b = *(const float4*)(kg + r * 64 + c);
        ks[r*68+c] = f2tf32(b.x); ks[r*68+c+1] = f2tf32(b.y);
        ks[r*68+c+2] = f2tf32(b.z); ks[r*68+c+3] = f2tf32(b.w);
        float4 d = *(const float4*)(vg + r * 64 + c);
        vs[r*68+c] = f2tf32(d.x); vs[r*68+c+1] = f2tf32(d.y);
        vs[r*68+c+2] = f2tf32(d.z); vs[r*68+c+3] = f2tf32(d.w);
    }
    __syncthreads();

    const int w = tid >> 5, lane = tid & 31;
    const int g = lane >> 2, tg = lane & 3;
    const int mr = w * 16;

    float c[8][4];
    #pragma unroll
    for (int in = 0; in < 8; in++)
        #pragma unroll
        for (int j = 0; j < 4; j++) c[in][j] = 0.f;

    // scores = q @ k^T
    #pragma unroll
    for (int kk = 0; kk < 64; kk += 8) {
        uint32_t a0 = qs[(mr + g    ) * 68 + kk + tg    ];
        uint32_t a1 = qs[(mr + g + 8) * 68 + kk + tg    ];
        uint32_t a2 = qs[(mr + g    ) * 68 + kk + tg + 4];
        uint32_t a3 = qs[(mr + g + 8) * 68 + kk + tg + 4];
        #pragma unroll
        for (int in = 0; in < 8; in++) {
            int nr = in * 8 + g;
            uint32_t b0 = ks[nr * 68 + kk + tg    ];
            uint32_t b1 = ks[nr * 68 + kk + tg + 4];
            mma_tf32(c[in], a0, a1, a2, a3, b0, b1);
        }
    }

    // softmax over the 64-wide row (scale 1/sqrt(64) = 1/8)
    const float scale = 0.125f;
    float mx0 = -1e30f, mx1 = -1e30f;
    #pragma unroll
    for (int in = 0; in < 8; in++) {
        c[in][0] *= scale; c[in][1] *= scale;
        c[in][2] *= scale; c[in][3] *= scale;
        mx0 = fmaxf(mx0, fmaxf(c[in][0], c[in][1]));
        mx1 = fmaxf(mx1, fmaxf(c[in][2], c[in][3]));
    }
    mx0 = fmaxf(mx0, __shfl_xor_sync(0xffffffffu, mx0, 1));
    mx0 = fmaxf(mx0, __shfl_xor_sync(0xffffffffu, mx0, 2));
    mx1 = fmaxf(mx1, __shfl_xor_sync(0xffffffffu, mx1, 1));
    mx1 = fmaxf(mx1, __shfl_xor_sync(0xffffffffu, mx1, 2));

    float s0 = 0.f, s1 = 0.f;
    #pragma unroll
    for (int in = 0; in < 8; in++) {
        c[in][0] = __expf(c[in][0] - mx0); s0 += c[in][0];
        c[in][1] = __expf(c[in][1] - mx0); s0 += c[in][1];
        c[in][2] = __expf(c[in][2] - mx1); s1 += c[in][2];
        c[in][3] = __expf(c[in][3] - mx1); s1 += c[in][3];
    }
    s0 += __shfl_xor_sync(0xffffffffu, s0, 1);
    s0 += __shfl_xor_sync(0xffffffffu, s0, 2);
    s1 += __shfl_xor_sync(0xffffffffu, s1, 1);
    s1 += __shfl_xor_sync(0xffffffffu, s1, 2);
    float inv0 = 1.f / s0, inv1 = 1.f / s1;

    // write normalized probs to ss as tf32 (warp-private rows)
    #pragma unroll
    for (int in = 0; in < 8; in++) {
        int col = in * 8 + 2 * tg;
        ss[(mr + g    ) * 68 + col    ] = f2tf32(c[in][0] * inv0);
        ss[(mr + g    ) * 68 + col + 1] = f2tf32(c[in][1] * inv0);
        ss[(mr + g + 8) * 68 + col    ] = f2tf32(c[in][2] * inv1);
        ss[(mr + g + 8) * 68 + col + 1] = f2tf32(c[in][3] * inv1);
    }
    __syncwarp();

    // out = p @ v   (A = p row-major, B[n=dk][k=m'] = v[m'][dk])
    #pragma unroll
    for (int in = 0; in < 8; in++)
        #pragma unroll
        for (int j = 0; j < 4; j++) c[in][j] = 0.f;

    #pragma unroll
    for (int kk = 0; kk < 64; kk += 8) {
        uint32_t a0 = ss[(mr + g    ) * 68 + kk + tg    ];
        uint32_t a1 = ss[(mr + g + 8) * 68 + kk + tg    ];
        uint32_t a2 = ss[(mr + g    ) * 68 + kk + tg + 4];
        uint32_t a3 = ss[(mr + g + 8) * 68 + kk + tg + 4];
        #pragma unroll
        for (int in = 0; in < 8; in++) {
            int nc = in * 8 + g;
            uint32_t b0 = vs[(kk + tg    ) * 68 + nc];
            uint32_t b1 = vs[(kk + tg + 4) * 68 + nc];
            mma_tf32(c[in], a0, a1, a2, a3, b0, b1);
        }
    }

    // store to g_a[(bt*64+m)*512 + h*64 + dk]
    float* dst = out_a + (size_t)bt * 64 * 512 + h * 64;
    #pragma unroll
    for (int in = 0; in < 8; in++) {
        int col = in * 8 + 2 * tg;
        dst[(size_t)(mr + g    ) * 512 + col    ] = c[in][0];
        dst[(size_t)(mr + g    ) * 512 + col + 1] = c[in][1];
        dst[(size_t)(mr + g + 8) * 512 + col    ] = c[in][2];
        dst[(size_t)(mr + g + 8) * 512 + col + 1] = c[in][3];
    }
}

// ---------------------------------------------------------------------------
extern "C" void kernel_launch(void* const* d_in, const int* in_sizes, int n_in,
                              void* d_out, int out_size)
{
    const float* x  = (const float*)d_in[0];
    const float* Wq = (const float*)d_in[1];
    const float* bq = (const float*)d_in[2];
    const float* Wk = (const float*)d_in[3];
    const float* bk = (const float*)d_in[4];
    const float* Wv = (const float*)d_in[5];
    const float* bv = (const float*)d_in[6];
    const float* Wo = (const float*)d_in[7];
    const float* bo = (const float*)d_in[8];
    float* out = (float*)d_out;

    void *pq, *pk, *pv, *pa;
    cudaGetSymbolAddress(&pq, g_q);
    cudaGetSymbolAddress(&pk, g_k);
    cudaGetSymbolAddress(&pv, g_v);
    cudaGetSymbolAddress(&pa, g_a);

    dim3 gg(8, NROWS / 128);   // x = n-tiles (8) inner so X tiles get L2 reuse
    gemm_tf32<0><<<gg, 256>>>(x, Wq, bq, (float*)pq);
    gemm_tf32<0><<<gg, 256>>>(x, Wk, bk, (float*)pk);
    gemm_tf32<0><<<gg, 256>>>(x, Wv, bv, (float*)pv);

    static_assert(4 * 64 * 68 * 4 == 69632, "smem size");
    cudaFuncSetAttribute(attn_kernel, cudaFuncAttributeMaxDynamicSharedMemorySize, 69632);
    attn_kernel<<<NBTH, 128, 69632>>>((float*)pa);

    gemm_tf32<1><<<gg, 256>>>((const float*)pa, Wo, bo, out);
}

// round 3
// speedup vs baseline: 2.2531x; 2.2531x over previous
#include <cuda_runtime.h>
#include <cuda_fp16.h>
#include <cstdint>

// Problem constants
#define BB 8
#define TT 256
#define MM 64
#define DD 512
#define HH 8
#define DKK 64
#define NROWS (BB*TT*MM)        // 131072
#define NBTH  (BB*TT*HH)        // 16384

// Scratch (device globals: allocation-free)
__device__ __half g_xh[(size_t)NROWS*DD];      // X in fp16
__device__ __half g_wqkv[3*DD*DD];             // packed Wq|Wk|Wv fp16 (rows = features)
__device__ __half g_wo[DD*DD];                 // Wo fp16
__device__ __half g_q[(size_t)NBTH*MM*DKK];    // (bt,h,m,dk) fp16
__device__ __half g_k[(size_t)NBTH*MM*DKK];
__device__ __half g_v[(size_t)NBTH*MM*DKK];
__device__ __half g_a[(size_t)NROWS*DD];       // (btm, d) fp16 attention output

__device__ __forceinline__ uint32_t smem_u32(const void* p) {
    uint32_t a;
    asm("{ .reg .u64 t; cvta.to.shared.u64 t, %1; cvt.u32.u64 %0, t; }" : "=r"(a) : "l"(p));
    return a;
}
__device__ __forceinline__ void cp16(uint32_t saddr, const void* gaddr) {
    asm volatile("cp.async.cg.shared.global [%0], [%1], 16;" :: "r"(saddr), "l"(gaddr) : "memory");
}
__device__ __forceinline__ void cp_commit() {
    asm volatile("cp.async.commit_group;" ::: "memory");
}

__device__ __forceinline__ void mma_f16(float* c,
    uint32_t a0, uint32_t a1, uint32_t a2, uint32_t a3, uint32_t b0, uint32_t b1)
{
    asm volatile(
        "mma.sync.aligned.m16n8k16.row.col.f32.f16.f16.f32 "
        "{%0,%1,%2,%3}, {%4,%5,%6,%7}, {%8,%9}, {%0,%1,%2,%3};"
        : "+f"(c[0]), "+f"(c[1]), "+f"(c[2]), "+f"(c[3])
        : "r"(a0), "r"(a1), "r"(a2), "r"(a3), "r"(b0), "r"(b1));
}

// ---------------------------------------------------------------------------
// conv: fp32 -> fp16 (rn), float4 -> 8 bytes
// ---------------------------------------------------------------------------
__global__ void conv_h(const float4* __restrict__ in, uint2* __restrict__ out, int n4)
{
    int i = blockIdx.x * blockDim.x + threadIdx.x;
    if (i >= n4) return;
    float4 v = in[i];
    __half2 h0 = __floats2half2_rn(v.x, v.y);
    __half2 h1 = __floats2half2_rn(v.z, v.w);
    uint2 r;
    r.x = *(uint32_t*)&h0;
    r.y = *(uint32_t*)&h1;
    out[i] = r;
}

// ---------------------------------------------------------------------------
// fp16 GEMM: D[128 x 128] block of Y = A(rows,512) @ B(cols,512)^T + bias
// 3-stage cp.async pipeline, BK=64, XOR-swizzled 128B smem rows.
// 8 warps (4x2), warp tile 32x64.
// MODE 0 (QKV fused, N=1536): store fp16 via smem to (bt,h,m,dk) in q/k/v.
// MODE 1 (out-proj): store fp32 direct to out[r*512+col].
// ---------------------------------------------------------------------------
#define STG 32768                 // per-stage bytes: A 16KB + B 16KB
#define GEMM_SMEM (3*STG)

__device__ __forceinline__ void fill_stage(uint32_t smem_base, int s,
                                           const __half* __restrict__ Ap,
                                           const __half* __restrict__ Bp,
                                           int kt, int tid)
{
    uint32_t As = smem_base + s * STG;
    uint32_t Bs = As + 16384;
    int koff = kt * 64;
    #pragma unroll
    for (int it = 0; it < 4; it++) {
        int i = tid + it * 256;
        int r = i >> 3, c8 = i & 7;
        cp16(As + r * 128 + ((c8 ^ (r & 7)) << 4), Ap + (size_t)r * 512 + koff + c8 * 8);
    }
    #pragma unroll
    for (int it = 0; it < 4; it++) {
        int i = tid + it * 256;
        int r = i >> 3, c8 = i & 7;
        cp16(Bs + r * 128 + ((c8 ^ (r & 7)) << 4), Bp + (size_t)r * 512 + koff + c8 * 8);
    }
    cp_commit();
}

template<int MODE>
__global__ __launch_bounds__(256, 2)
void gemm_f16(const __half* __restrict__ A, const __half* __restrict__ Bw,
              const float* __restrict__ bq, const float* __restrict__ bk,
              const float* __restrict__ bv,
              void* __restrict__ dq, void* __restrict__ dk_, void* __restrict__ dv)
{
    extern __shared__ char sm[];
    const int tid = threadIdx.x, wid = tid >> 5, lane = tid & 31;
    const int g = lane >> 2, tg = lane & 3;
    const int n0 = blockIdx.x * 128, m0 = blockIdx.y * 128;
    const int wm = (wid & 3) * 32, wn = (wid >> 2) * 64;

    uint32_t sbase = smem_u32(sm);
    const __half* Ap = A + (size_t)m0 * 512;
    const __half* Bp = Bw + (size_t)n0 * 512;

    float acc[2][8][4];
    #pragma unroll
    for (int a = 0; a < 2; a++)
        #pragma unroll
        for (int b = 0; b < 8; b++)
            #pragma unroll
            for (int c = 0; c < 4; c++) acc[a][b][c] = 0.f;

    fill_stage(sbase, 0, Ap, Bp, 0, tid);
    fill_stage(sbase, 1, Ap, Bp, 1, tid);

    for (int kt = 0; kt < 8; kt++) {
        if (kt < 7) asm volatile("cp.async.wait_group 1;" ::: "memory");
        else        asm volatile("cp.async.wait_group 0;" ::: "memory");
        __syncthreads();
        if (kt + 2 < 8) fill_stage(sbase, (kt + 2) % 3, Ap, Bp, kt + 2, tid);

        char* As = sm + (kt % 3) * STG;
        char* Bs = As + 16384;

        #pragma unroll
        for (int ks = 0; ks < 4; ks++) {
            int c0 = ks * 2;
            uint32_t af[2][4], bf[8][2];
            #pragma unroll
            for (int im = 0; im < 2; im++) {
                int r = wm + im * 16 + g;
                char* p0 = As + r * 128 + 4 * tg;
                char* p1 = As + (r + 8) * 128 + 4 * tg;
                af[im][0] = *(uint32_t*)(p0 + ((c0       ^ g) << 4));
                af[im][1] = *(uint32_t*)(p1 + ((c0       ^ g) << 4));
                af[im][2] = *(uint32_t*)(p0 + (((c0 + 1) ^ g) << 4));
                af[im][3] = *(uint32_t*)(p1 + (((c0 + 1) ^ g) << 4));
            }
            #pragma unroll
            for (int in = 0; in < 8; in++) {
                int n = wn + in * 8 + g;
                char* p = Bs + n * 128 + 4 * tg;
                bf[in][0] = *(uint32_t*)(p + ((c0       ^ g) << 4));
                bf[in][1] = *(uint32_t*)(p + (((c0 + 1) ^ g) << 4));
            }
            #pragma unroll
            for (int im = 0; im < 2; im++)
                #pragma unroll
                for (int in = 0; in < 8; in++)
                    mma_f16(acc[im][in], af[im][0], af[im][1], af[im][2], af[im][3],
                            bf[in][0], bf[in][1]);
        }
        __syncthreads();
    }

    if (MODE == 0) {
        // pick tensor + bias by n-block
        int t = n0 >> 9, nc0 = n0 & 511, h0 = nc0 >> 6;
        const float* bias = (t == 0 ? bq : t == 1 ? bk : bv) + nc0;
        __half* dst_t = (__half*)(t == 0 ? dq : t == 1 ? dk_ : dv);

        // acc (+bias) -> smem fp16 tile Cs[128][136]
        #pragma unroll
        for (int im = 0; im < 2; im++) {
            #pragma unroll
            for (int in = 0; in < 8; in++) {
                int col = wn + in * 8 + 2 * tg;
                float bb0 = bias[col], bb1 = bias[col + 1];
                int r0 = wm + im * 16 + g;
                *(__half2*)(sm + r0 * 272 + col * 2) =
                    __floats2half2_rn(acc[im][in][0] + bb0, acc[im][in][1] + bb1);
                *(__half2*)(sm + (r0 + 8) * 272 + col * 2) =
                    __floats2half2_rn(acc[im][in][2] + bb0, acc[im][in][3] + bb1);
            }
        }
        __syncthreads();

        // coalesced stores: thread = (m, h-block); 64 contiguous halves each
        int m = tid >> 1, hb = tid & 1;
        int r = m0 + m, bt = r >> 6, mm = r & 63;
        __half* dst = dst_t + (((size_t)(bt * 8 + h0 + hb) * 64 + mm) * 64);
        const uint4* srcp = (const uint4*)(sm + m * 272 + hb * 128);
        uint4* dstp = (uint4*)dst;
        #pragma unroll
        for (int j = 0; j < 8; j++) dstp[j] = srcp[j];
    } else {
        // direct fp32 stores
        float* out = (float*)dq;
        const float* bias = bq;
        #pragma unroll
        for (int im = 0; im < 2; im++) {
            #pragma unroll
            for (int in = 0; in < 8; in++) {
                int col = n0 + wn + in * 8 + 2 * tg;
                float bb0 = bias[col], bb1 = bias[col + 1];
                int r0 = m0 + wm + im * 16 + g;
                float2 v0 = {acc[im][in][0] + bb0, acc[im][in][1] + bb1};
                float2 v1 = {acc[im][in][2] + bb0, acc[im][in][3] + bb1};
                *(float2*)(out + (size_t)r0 * 512 + col) = v0;
                *(float2*)(out + (size_t)(r0 + 8) * 512 + col) = v1;
            }
        }
    }
}

// ---------------------------------------------------------------------------
// Attention (fp16): one CTA per (bt, h). q,k,v tiles (bt,h,m,dk) fp16.
// scores = q@k^T/8 -> softmax -> p@v. Writes g_a[(btm, d)] fp16.
// ---------------------------------------------------------------------------
__global__ __launch_bounds__(128)
void attn_kernel()
{
    __shared__ __half qs[64 * 72];
    __shared__ __half ks_[64 * 72];
    __shared__ __half vs[64 * 72];   // [dk][m'] (transposed)
    __shared__ __half ss[64 * 72];   // P [m][m']

    const int bth = blockIdx.x;
    const int bt = bth >> 3, h = bth & 7;
    const __half* qg = g_q + (size_t)bth * 4096;
    const __half* kg = g_k + (size_t)bth * 4096;
    const __half* vg = g_v + (size_t)bth * 4096;

    const int tid = threadIdx.x;

    // stage q,k (direct [m][dk]) and v (transpose -> [dk][m'])
    #pragma unroll
    for (int it = 0; it < 4; it++) {
        int i = tid + it * 128;
        int r = i >> 3, c8 = i & 7;
        *(uint4*)(qs + r * 72 + c8 * 8) = *(const uint4*)(qg + r * 64 + c8 * 8);
        *(uint4*)(ks_ + r * 72 + c8 * 8) = *(const uint4*)(kg + r * 64 + c8 * 8);
        uint4 vv = *(const uint4*)(vg + r * 64 + c8 * 8);
        const __half* hv = (const __half*)&vv;
        #pragma unroll
        for (int j = 0; j < 8; j++) vs[(c8 * 8 + j) * 72 + r] = hv[j];
    }
    __syncthreads();

    const int w = tid >> 5, lane = tid & 31;
    const int g = lane >> 2, tg = lane & 3;
    const int mr = w * 16;

    float c[8][4];
    #pragma unroll
    for (int in = 0; in < 8; in++)
        #pragma unroll
        for (int j = 0; j < 4; j++) c[in][j] = 0.f;

    // scores = q @ k^T  (A = qs[m][dk], B = ks[m'][dk], k-major both)
    #pragma unroll
    for (int ks4 = 0; ks4 < 4; ks4++) {
        int koff = ks4 * 16;
        uint32_t a0 = *(uint32_t*)(qs + (mr + g    ) * 72 + koff + 2 * tg);
        uint32_t a1 = *(uint32_t*)(qs + (mr + g + 8) * 72 + koff + 2 * tg);
        uint32_t a2 = *(uint32_t*)(qs + (mr + g    ) * 72 + koff + 2 * tg + 8);
        uint32_t a3 = *(uint32_t*)(qs + (mr + g + 8) * 72 + koff + 2 * tg + 8);
        #pragma unroll
        for (int in = 0; in < 8; in++) {
            int nr = in * 8 + g;
            uint32_t b0 = *(uint32_t*)(ks_ + nr * 72 + koff + 2 * tg);
            uint32_t b1 = *(uint32_t*)(ks_ + nr * 72 + koff + 2 * tg + 8);
            mma_f16(c[in], a0, a1, a2, a3, b0, b1);
        }
    }

    const float scale = 0.125f;
    float mx0 = -1e30f, mx1 = -1e30f;
    #pragma unroll
    for (int in = 0; in < 8; in++) {
        c[in][0] *= scale; c[in][1] *= scale;
        c[in][2] *= scale; c[in][3] *= scale;
        mx0 = fmaxf(mx0, fmaxf(c[in][0], c[in][1]));
        mx1 = fmaxf(mx1, fmaxf(c[in][2], c[in][3]));
    }
    mx0 = fmaxf(mx0, __shfl_xor_sync(0xffffffffu, mx0, 1));
    mx0 = fmaxf(mx0, __shfl_xor_sync(0xffffffffu, mx0, 2));
    mx1 = fmaxf(mx1, __shfl_xor_sync(0xffffffffu, mx1, 1));
    mx1 = fmaxf(mx1, __shfl_xor_sync(0xffffffffu, mx1, 2));

    float s0 = 0.f, s1 = 0.f;
    #pragma unroll
    for (int in = 0; in < 8; in++) {
        c[in][0] = __expf(c[in][0] - mx0); s0 += c[in][0];
        c[in][1] = __expf(c[in][1] - mx0); s0 += c[in][1];
        c[in][2] = __expf(c[in][2] - mx1); s1 += c[in][2];
        c[in][3] = __expf(c[in][3] - mx1); s1 += c[in][3];
    }
    s0 += __shfl_xor_sync(0xffffffffu, s0, 1);
    s0 += __shfl_xor_sync(0xffffffffu, s0, 2);
    s1 += __shfl_xor_sync(0xffffffffu, s1, 1);
    s1 += __shfl_xor_sync(0xffffffffu, s1, 2);
    float inv0 = 1.f / s0, inv1 = 1.f / s1;

    #pragma unroll
    for (int in = 0; in < 8; in++) {
        int col = in * 8 + 2 * tg;
        *(__half2*)(ss + (mr + g    ) * 72 + col) = __floats2half2_rn(c[in][0] * inv0, c[in][1] * inv0);
        *(__half2*)(ss + (mr + g + 8) * 72 + col) = __floats2half2_rn(c[in][2] * inv1, c[in][3] * inv1);
    }
    __syncwarp();

    #pragma unroll
    for (int in = 0; in < 8; in++)
        #pragma unroll
        for (int j = 0; j < 4; j++) c[in][j] = 0.f;

    // out = P @ V  (A = ss[m][m'], B[k=m'][n=dk] = vs[dk][m'])
    #pragma unroll
    for (int ks4 = 0; ks4 < 4; ks4++) {
        int koff = ks4 * 16;
        uint32_t a0 = *(uint32_t*)(ss + (mr + g    ) * 72 + koff + 2 * tg);
        uint32_t a1 = *(uint32_t*)(ss + (mr + g + 8) * 72 + koff + 2 * tg);
        uint32_t a2 = *(uint32_t*)(ss + (mr + g    ) * 72 + koff + 2 * tg + 8);
        uint32_t a3 = *(uint32_t*)(ss + (mr + g + 8) * 72 + koff + 2 * tg + 8);
        #pragma unroll
        for (int in = 0; in < 8; in++) {
            int nr = in * 8 + g;
            uint32_t b0 = *(uint32_t*)(vs + nr * 72 + koff + 2 * tg);
            uint32_t b1 = *(uint32_t*)(vs + nr * 72 + koff + 2 * tg + 8);
            mma_f16(c[in], a0, a1, a2, a3, b0, b1);
        }
    }

    // store fp16 to g_a[(bt*64+m)*512 + h*64 + col]
    __half* dst = g_a + ((size_t)bt * 64) * 512 + h * 64;
    #pragma unroll
    for (int in = 0; in < 8; in++) {
        int col = in * 8 + 2 * tg;
        *(__half2*)(dst + (size_t)(mr + g    ) * 512 + col) = __floats2half2_rn(c[in][0], c[in][1]);
        *(__half2*)(dst + (size_t)(mr + g + 8) * 512 + col) = __floats2half2_rn(c[in][2], c[in][3]);
    }
}

// ---------------------------------------------------------------------------
extern "C" void kernel_launch(void* const* d_in, const int* in_sizes, int n_in,
                              void* d_out, int out_size)
{
    const float* x  = (const float*)d_in[0];
    const float* Wq = (const float*)d_in[1];
    const float* bq = (const float*)d_in[2];
    const float* Wk = (const float*)d_in[3];
    const float* bk = (const float*)d_in[4];
    const float* Wv = (const float*)d_in[5];
    const float* bv = (const float*)d_in[6];
    const float* Wo = (const float*)d_in[7];
    const float* bo = (const float*)d_in[8];
    float* out = (float*)d_out;

    void *pxh, *pwqkv, *pwo, *pq, *pk, *pv, *pa;
    cudaGetSymbolAddress(&pxh,   g_xh);
    cudaGetSymbolAddress(&pwqkv, g_wqkv);
    cudaGetSymbolAddress(&pwo,   g_wo);
    cudaGetSymbolAddress(&pq,    g_q);
    cudaGetSymbolAddress(&pk,    g_k);
    cudaGetSymbolAddress(&pv,    g_v);
    cudaGetSymbolAddress(&pa,    g_a);
    __half* wqkv = (__half*)pwqkv;

    // 1) fp32 -> fp16 conversions
    conv_h<<<(NROWS*DD/4 + 255)/256, 256>>>((const float4*)x,  (uint2*)pxh, NROWS*DD/4);
    conv_h<<<(DD*DD/4 + 255)/256, 256>>>((const float4*)Wq, (uint2*)(wqkv),            DD*DD/4);
    conv_h<<<(DD*DD/4 + 255)/256, 256>>>((const float4*)Wk, (uint2*)(wqkv + DD*DD),    DD*DD/4);
    conv_h<<<(DD*DD/4 + 255)/256, 256>>>((const float4*)Wv, (uint2*)(wqkv + 2*DD*DD),  DD*DD/4);
    conv_h<<<(DD*DD/4 + 255)/256, 256>>>((const float4*)Wo, (uint2*)pwo,               DD*DD/4);

    cudaFuncSetAttribute(gemm_f16<0>, cudaFuncAttributeMaxDynamicSharedMemorySize, GEMM_SMEM);
    cudaFuncSetAttribute(gemm_f16<1>, cudaFuncAttributeMaxDynamicSharedMemorySize, GEMM_SMEM);

    // 2) fused QKV projection: N = 1536
    dim3 gqkv(12, NROWS / 128);
    gemm_f16<0><<<gqkv, 256, GEMM_SMEM>>>((const __half*)pxh, wqkv,
                                          bq, bk, bv, pq, pk, pv);

    // 3) attention
    attn_kernel<<<NBTH, 128>>>();

    // 4) output projection: N = 512, fp32 out
    dim3 go(4, NROWS / 128);
    gemm_f16<1><<<go, 256, GEMM_SMEM>>>((const __half*)pa, (const __half*)pwo,
                                        bo, nullptr, nullptr, out, nullptr, nullptr);
}